// round 13
// baseline (speedup 1.0000x reference)
#include <cuda_runtime.h>
#include <cuda_fp16.h>
#include <cstdint>

#define BATCH 64
#define T 512
#define C 384
#define H 64
#define BT (BATCH*T)

// Q, K, V projected to fp16, row-major [row*H + col].
__device__ __half g_Q[BT * H];
__device__ __half g_K[BT * H];
__device__ __half g_V[BT * H];
// Weights pre-packed to fp16 half2 pairs along k: [mat][k2][n].
__device__ uint32_t g_W16[3 * 192 * 64];

__device__ __forceinline__ uint32_t pack_h2(float a, float b) {
    __half2 h = __floats2half2_rn(a, b);
    return *(uint32_t*)&h;
}

__device__ __forceinline__ void mma_f16(float c[4], const uint32_t a[4],
                                        uint32_t b0, uint32_t b1) {
    asm volatile(
        "mma.sync.aligned.m16n8k16.row.col.f32.f16.f16.f32 "
        "{%0,%1,%2,%3}, {%4,%5,%6,%7}, {%8,%9}, {%0,%1,%2,%3};\n"
        : "+f"(c[0]), "+f"(c[1]), "+f"(c[2]), "+f"(c[3])
        : "r"(a[0]), "r"(a[1]), "r"(a[2]), "r"(a[3]), "r"(b0), "r"(b1));
}

// ---------------------------------------------------------------------------
// Kernel 0: pack W fp32 -> fp16 half2 pairs along k. 36864 elements.
// ---------------------------------------------------------------------------
__global__ __launch_bounds__(256) void pack_w_kernel(
    const float* __restrict__ Wq,
    const float* __restrict__ Wk,
    const float* __restrict__ Wv)
{
    int idx = blockIdx.x * 256 + threadIdx.x;      // 144 blocks exactly
    int mat = idx / (192 * 64);
    int rem = idx - mat * (192 * 64);
    int k2 = rem >> 6;
    int n  = rem & 63;
    const float* W = (mat == 0) ? Wq : ((mat == 1) ? Wk : Wv);
    g_W16[idx] = pack_h2(W[(2 * k2) * H + n], W[(2 * k2 + 1) * H + n]);
}

// ---------------------------------------------------------------------------
// Kernel 1: fused QKV projection, fp16 m16n8k16, 512 threads = 16 warps
// as 8(M) x 2(N); warp tile 16 rows x 32 cols x 3 mats (A frags reused 3x).
// x read once chip-wide; x/W tiles double-buffered; 1 barrier/kt.
// ALL outputs row-major fp16 (coalesced uint32 stores, same as round 11).
// Grid: BT/128 = 256 blocks.
// ---------------------------------------------------------------------------
#define AS2_STR 20
#define WT_STR 68

__global__ __launch_bounds__(512) void qkv_proj_kernel(const float* __restrict__ x)
{
    __shared__ uint32_t As2[2][128][AS2_STR];      // x tile fp16 pairs [m][k2]
    __shared__ uint32_t Wt[2][3][16][WT_STR];      // W tiles [mat][k2][n]

    const int tid  = threadIdx.x;
    const int lane = tid & 31;
    const int wid  = tid >> 5;
    const int warpM = wid & 7;      // 0..7 -> 16-row group
    const int warpN = wid >> 3;     // 0..1 -> 32-col group
    const int g  = lane >> 2;
    const int tg = lane & 3;
    const int row0 = blockIdx.x * 128;

    float c[3][4][4];
    #pragma unroll
    for (int mat = 0; mat < 3; ++mat)
        #pragma unroll
        for (int nf = 0; nf < 4; ++nf)
            #pragma unroll
            for (int j = 0; j < 4; ++j) c[mat][nf][j] = 0.0f;

    // initial tiles (kt=0) into buf 0
    #pragma unroll
    for (int i = 0; i < 2; ++i) {
        int s = tid + i * 512;
        int r = s >> 3;
        int c4 = (s & 7) * 4;
        float4 v = *(const float4*)&x[(row0 + r) * C + c4];
        *(uint2*)&As2[0][r][c4 >> 1] = make_uint2(pack_h2(v.x, v.y), pack_h2(v.z, v.w));
    }
    for (int s = tid; s < 768; s += 512) {
        int mat = s >> 8, k2 = (s >> 4) & 15, n4 = (s & 15) * 4;
        *(uint4*)&Wt[0][mat][k2][n4] =
            *(const uint4*)&g_W16[mat * (192 * 64) + k2 * 64 + n4];
    }

    for (int kt = 0; kt < 12; ++kt) {
        const int buf = kt & 1;
        __syncthreads();

        float4 xv[2];
        uint4 wv[2];
        const bool pf = (kt < 11);
        const bool w2 = (tid < 256);
        if (pf) {
            #pragma unroll
            for (int i = 0; i < 2; ++i) {
                int s = tid + i * 512;
                int r = s >> 3;
                int c4 = (s & 7) * 4;
                xv[i] = *(const float4*)&x[(row0 + r) * C + (kt + 1) * 32 + c4];
            }
            {
                int s = tid;
                int mat = s >> 8, k2 = (s >> 4) & 15, n4 = (s & 15) * 4;
                wv[0] = *(const uint4*)&g_W16[mat * (192 * 64) + ((kt + 1) * 16 + k2) * 64 + n4];
            }
            if (w2) {
                int s = tid + 512;
                int mat = s >> 8, k2 = (s >> 4) & 15, n4 = (s & 15) * 4;
                wv[1] = *(const uint4*)&g_W16[mat * (192 * 64) + ((kt + 1) * 16 + k2) * 64 + n4];
            }
        }

        #pragma unroll
        for (int ks = 0; ks < 2; ++ks) {
            const int p = ks * 8 + tg;
            uint32_t a[4];
            {
                int r = warpM * 16 + g;
                a[0] = As2[buf][r][p];
                a[1] = As2[buf][r + 8][p];
                a[2] = As2[buf][r][p + 4];
                a[3] = As2[buf][r + 8][p + 4];
            }
            #pragma unroll
            for (int mat = 0; mat < 3; ++mat) {
                #pragma unroll
                for (int nf = 0; nf < 4; ++nf) {
                    int n = warpN * 32 + nf * 8 + g;
                    uint32_t b0 = Wt[buf][mat][p][n];
                    uint32_t b1 = Wt[buf][mat][p + 4][n];
                    mma_f16(c[mat][nf], a, b0, b1);
                }
            }
        }

        if (pf) {
            #pragma unroll
            for (int i = 0; i < 2; ++i) {
                int s = tid + i * 512;
                int r = s >> 3;
                int c4 = (s & 7) * 4;
                *(uint2*)&As2[buf ^ 1][r][c4 >> 1] =
                    make_uint2(pack_h2(xv[i].x, xv[i].y), pack_h2(xv[i].z, xv[i].w));
            }
            {
                int s = tid;
                int mat = s >> 8, k2 = (s >> 4) & 15, n4 = (s & 15) * 4;
                *(uint4*)&Wt[buf ^ 1][mat][k2][n4] = wv[0];
            }
            if (w2) {
                int s = tid + 512;
                int mat = s >> 8, k2 = (s >> 4) & 15, n4 = (s & 15) * 4;
                *(uint4*)&Wt[buf ^ 1][mat][k2][n4] = wv[1];
            }
        }
    }

    const int r = row0 + warpM * 16 + g;
    #pragma unroll
    for (int mat = 0; mat < 3; ++mat) {
        __half* O = (mat == 0) ? g_Q : ((mat == 1) ? g_K : g_V);
        #pragma unroll
        for (int nf = 0; nf < 4; ++nf) {
            int col = warpN * 32 + nf * 8 + 2 * tg;
            *(uint32_t*)&O[r * H + col]       = pack_h2(c[mat][nf][0], c[mat][nf][1]);
            *(uint32_t*)&O[(r + 8) * H + col] = pack_h2(c[mat][nf][2], c[mat][nf][3]);
        }
    }
}

// ---------------------------------------------------------------------------
// Kernel 2: causal flash attention — round-11 version VERBATIM.
// 128 q-rows per block (8 warps, 256 thr), double-buffered K/V, P in
// registers, one barrier per tile. 256 blocks, balanced co-residency.
// ---------------------------------------------------------------------------
#define Q2_STR 36
#define K2_STR 36
#define V2_STR 72
#define ATTN_SMEM_U32 (128 * Q2_STR + 2 * 64 * K2_STR + 2 * 32 * V2_STR)
#define ATTN_SMEM_BYTES (ATTN_SMEM_U32 * 4)

__global__ __launch_bounds__(256) void attn_kernel(float* __restrict__ out)
{
    extern __shared__ uint32_t sm_at[];
    uint32_t* Qs2 = sm_at;                               // [128][36]
    uint32_t (*K2)[64 * K2_STR] =
        (uint32_t (*)[64 * K2_STR])(sm_at + 128 * Q2_STR);
    uint32_t (*V2)[32 * V2_STR] =
        (uint32_t (*)[32 * V2_STR])(sm_at + 128 * Q2_STR + 2 * 64 * K2_STR);

    const int tid  = threadIdx.x;
    const int lane = tid & 31;
    const int wid  = tid >> 5;
    const int g    = lane >> 2;
    const int tg   = lane & 3;

    int bid = blockIdx.x;
    int b, qb;
    if (bid < 148) { qb = bid & 3; b = bid >> 2; }
    else { int s = bid - 148; qb = 3 - (s & 3); b = 37 + (s >> 2); }

    const int tmax = 2 * qb + 1;
    const float scale = 0.125f;

    // ---- Q tile ----
    {
        const uint4* qsrc = (const uint4*)(g_Q + (b * T + qb * 128) * H);
        #pragma unroll
        for (int i = 0; i < 4; ++i) {
            int s = tid + i * 256;
            int r = s >> 3;
            int c4 = (s & 7) * 4;
            *(uint4*)&Qs2[r * Q2_STR + c4] = qsrc[s];
        }
    }
    // ---- K/V tile 0 into buf 0 ----
    {
        const uint4* ksrc = (const uint4*)(g_K + (b * T) * H);
        #pragma unroll
        for (int i = 0; i < 2; ++i) {
            int s = tid + i * 256;
            *(uint4*)&K2[0][(s >> 3) * K2_STR + (s & 7) * 4] = ksrc[s];
        }
        {
            int k2 = tid >> 3;
            int h0 = (tid & 7) * 8;
            const __half* vb = g_V + (b * T + 2 * k2) * H + h0;
            uint4 ea = *(const uint4*)vb;
            uint4 eb = *(const uint4*)(vb + H);
            uint32_t* dst = &V2[0][k2 * V2_STR + h0];
            *(uint4*)&dst[0] = make_uint4(
                __byte_perm(ea.x, eb.x, 0x5410), __byte_perm(ea.x, eb.x, 0x7632),
                __byte_perm(ea.y, eb.y, 0x5410), __byte_perm(ea.y, eb.y, 0x7632));
            *(uint4*)&dst[4] = make_uint4(
                __byte_perm(ea.z, eb.z, 0x5410), __byte_perm(ea.z, eb.z, 0x7632),
                __byte_perm(ea.w, eb.w, 0x5410), __byte_perm(ea.w, eb.w, 0x7632));
        }
    }
    __syncthreads();

    // ---- Q fragments (register resident) ----
    uint32_t qa[4][4];
    const int qrow = wid * 16 + g;
    #pragma unroll
    for (int ks = 0; ks < 4; ++ks) {
        int p = ks * 8 + tg;
        qa[ks][0] = Qs2[qrow * Q2_STR + p];
        qa[ks][1] = Qs2[(qrow + 8) * Q2_STR + p];
        qa[ks][2] = Qs2[qrow * Q2_STR + p + 4];
        qa[ks][3] = Qs2[(qrow + 8) * Q2_STR + p + 4];
    }

    float m[2] = {-1e30f, -1e30f};
    float l[2] = {0.0f, 0.0f};
    float o[8][4];
    #pragma unroll
    for (int nf = 0; nf < 8; ++nf)
        #pragma unroll
        for (int j = 0; j < 4; ++j) o[nf][j] = 0.0f;

    const int rowg0 = qb * 128 + wid * 16 + g;

    for (int t = 0; t <= tmax; ++t) {
        const int buf = t & 1;
        const bool pf = (t < tmax);

        uint4 kp[2], ve, vo;
        if (pf) {
            const uint4* ksrc = (const uint4*)(g_K + (b * T + (t + 1) * 64) * H);
            #pragma unroll
            for (int i = 0; i < 2; ++i) kp[i] = ksrc[tid + i * 256];
            {
                int k2 = tid >> 3;
                int h0 = (tid & 7) * 8;
                const __half* vb = g_V + (b * T + (t + 1) * 64 + 2 * k2) * H + h0;
                ve = *(const uint4*)vb;
                vo = *(const uint4*)(vb + H);
            }
        }

        // --- S = Q K^T ---
        float sf[8][4];
        #pragma unroll
        for (int nf = 0; nf < 8; ++nf)
            #pragma unroll
            for (int j = 0; j < 4; ++j) sf[nf][j] = 0.0f;

        #pragma unroll
        for (int ks = 0; ks < 4; ++ks) {
            const int p = ks * 8 + tg;
            #pragma unroll
            for (int nf = 0; nf < 8; ++nf) {
                int key = nf * 8 + g;
                mma_f16(sf[nf], qa[ks],
                        K2[buf][key * K2_STR + p], K2[buf][key * K2_STR + p + 4]);
            }
        }

        if (pf) {
            #pragma unroll
            for (int i = 0; i < 2; ++i) {
                int s = tid + i * 256;
                *(uint4*)&K2[buf ^ 1][(s >> 3) * K2_STR + (s & 7) * 4] = kp[i];
            }
            {
                int k2 = tid >> 3;
                int h0 = (tid & 7) * 8;
                uint32_t* dst = &V2[buf ^ 1][k2 * V2_STR + h0];
                *(uint4*)&dst[0] = make_uint4(
                    __byte_perm(ve.x, vo.x, 0x5410), __byte_perm(ve.x, vo.x, 0x7632),
                    __byte_perm(ve.y, vo.y, 0x5410), __byte_perm(ve.y, vo.y, 0x7632));
                *(uint4*)&dst[4] = make_uint4(
                    __byte_perm(ve.z, vo.z, 0x5410), __byte_perm(ve.z, vo.z, 0x7632),
                    __byte_perm(ve.w, vo.w, 0x5410), __byte_perm(ve.w, vo.w, 0x7632));
            }
        }

        // --- online softmax ---
        const bool maskit = (t >= 2 * qb);
        float mnew[2] = {m[0], m[1]};
        #pragma unroll
        for (int nf = 0; nf < 8; ++nf)
            #pragma unroll
            for (int j = 0; j < 4; ++j) {
                int rr = j >> 1;
                float v = sf[nf][j] * scale;
                if (maskit) {
                    int col = t * 64 + nf * 8 + 2 * tg + (j & 1);
                    int row = rowg0 + rr * 8;
                    if (col > row) v = -1e30f;
                }
                sf[nf][j] = v;
                mnew[rr] = fmaxf(mnew[rr], v);
            }
        #pragma unroll
        for (int rr = 0; rr < 2; ++rr) {
            mnew[rr] = fmaxf(mnew[rr], __shfl_xor_sync(0xffffffffu, mnew[rr], 1));
            mnew[rr] = fmaxf(mnew[rr], __shfl_xor_sync(0xffffffffu, mnew[rr], 2));
        }
        float alpha[2];
        #pragma unroll
        for (int rr = 0; rr < 2; ++rr) {
            alpha[rr] = __expf(m[rr] - mnew[rr]);
            m[rr] = mnew[rr];
        }
        float ls[2] = {0.0f, 0.0f};
        #pragma unroll
        for (int nf = 0; nf < 8; ++nf)
            #pragma unroll
            for (int j = 0; j < 4; ++j) {
                int rr = j >> 1;
                float pexp = __expf(sf[nf][j] - m[rr]);
                sf[nf][j] = pexp;
                ls[rr] += pexp;
            }
        #pragma unroll
        for (int rr = 0; rr < 2; ++rr) {
            ls[rr] += __shfl_xor_sync(0xffffffffu, ls[rr], 1);
            ls[rr] += __shfl_xor_sync(0xffffffffu, ls[rr], 2);
            l[rr] = l[rr] * alpha[rr] + ls[rr];
        }
        #pragma unroll
        for (int nf = 0; nf < 8; ++nf) {
            o[nf][0] *= alpha[0];
            o[nf][1] *= alpha[0];
            o[nf][2] *= alpha[1];
            o[nf][3] *= alpha[1];
        }

        // --- O += P V ---
        #pragma unroll
        for (int ks = 0; ks < 4; ++ks) {
            uint32_t pa[4];
            pa[0] = pack_h2(sf[2 * ks][0],     sf[2 * ks][1]);
            pa[1] = pack_h2(sf[2 * ks][2],     sf[2 * ks][3]);
            pa[2] = pack_h2(sf[2 * ks + 1][0], sf[2 * ks + 1][1]);
            pa[3] = pack_h2(sf[2 * ks + 1][2], sf[2 * ks + 1][3]);
            #pragma unroll
            for (int nf = 0; nf < 8; ++nf) {
                int hh = nf * 8 + g;
                mma_f16(o[nf], pa,
                        V2[buf][(ks * 8 + tg) * V2_STR + hh],
                        V2[buf][(ks * 8 + tg + 4) * V2_STR + hh]);
            }
        }

        __syncthreads();
    }

    const float inv0 = 1.0f / l[0];
    const float inv1 = 1.0f / l[1];
    const int grow = b * T + qb * 128 + wid * 16 + g;
    #pragma unroll
    for (int nf = 0; nf < 8; ++nf) {
        int col = nf * 8 + 2 * tg;
        *(float2*)&out[grow * H + col] =
            make_float2(o[nf][0] * inv0, o[nf][1] * inv0);
        *(float2*)&out[(grow + 8) * H + col] =
            make_float2(o[nf][2] * inv1, o[nf][3] * inv1);
    }
}

// ---------------------------------------------------------------------------
extern "C" void kernel_launch(void* const* d_in, const int* in_sizes, int n_in,
                              void* d_out, int out_size)
{
    const float* x  = (const float*)d_in[0];
    const float* Wq = (const float*)d_in[1];
    const float* Wk = (const float*)d_in[2];
    const float* Wv = (const float*)d_in[3];
    float* out = (float*)d_out;

    pack_w_kernel<<<144, 256>>>(Wq, Wk, Wv);

    qkv_proj_kernel<<<BT / 128, 512>>>(x);

    cudaFuncSetAttribute(attn_kernel,
                         cudaFuncAttributeMaxDynamicSharedMemorySize,
                         ATTN_SMEM_BYTES);
    attn_kernel<<<256, 256, ATTN_SMEM_BYTES>>>(out);
}

// round 14
// speedup vs baseline: 1.1060x; 1.1060x over previous
#include <cuda_runtime.h>
#include <cuda_fp16.h>
#include <cstdint>

#define BATCH 64
#define T 512
#define C 384
#define H 64
#define BT (BATCH*T)

// Q, K, V projected to fp16, row-major [row*H + col].
__device__ __half g_Q[BT * H];
__device__ __half g_K[BT * H];
__device__ __half g_V[BT * H];
// Weights pre-packed to fp16 half2 pairs along k: [mat][k2][n].
__device__ uint32_t g_W16[3 * 192 * 64];

__device__ __forceinline__ uint32_t pack_h2(float a, float b) {
    __half2 h = __floats2half2_rn(a, b);
    return *(uint32_t*)&h;
}

__device__ __forceinline__ void mma_f16(float c[4], const uint32_t a[4],
                                        uint32_t b0, uint32_t b1) {
    asm volatile(
        "mma.sync.aligned.m16n8k16.row.col.f32.f16.f16.f32 "
        "{%0,%1,%2,%3}, {%4,%5,%6,%7}, {%8,%9}, {%0,%1,%2,%3};\n"
        : "+f"(c[0]), "+f"(c[1]), "+f"(c[2]), "+f"(c[3])
        : "r"(a[0]), "r"(a[1]), "r"(a[2]), "r"(a[3]), "r"(b0), "r"(b1));
}

__device__ __forceinline__ uint32_t smem_addr_u32(const void* p) {
    return (uint32_t)__cvta_generic_to_shared(p);
}

__device__ __forceinline__ void cp_async16(uint32_t dst, const void* src) {
    asm volatile("cp.async.cg.shared.global [%0], [%1], 16;\n"
                 :: "r"(dst), "l"(src) : "memory");
}
__device__ __forceinline__ void cp_async_commit() {
    asm volatile("cp.async.commit_group;\n" ::: "memory");
}
__device__ __forceinline__ void cp_async_wait0() {
    asm volatile("cp.async.wait_group 0;\n" ::: "memory");
}

// ---------------------------------------------------------------------------
// Kernel 0: pack W fp32 -> fp16 half2 pairs along k. 36864 elements.
// ---------------------------------------------------------------------------
__global__ __launch_bounds__(256) void pack_w_kernel(
    const float* __restrict__ Wq,
    const float* __restrict__ Wk,
    const float* __restrict__ Wv)
{
    int idx = blockIdx.x * 256 + threadIdx.x;      // 144 blocks exactly
    int mat = idx / (192 * 64);
    int rem = idx - mat * (192 * 64);
    int k2 = rem >> 6;
    int n  = rem & 63;
    const float* W = (mat == 0) ? Wq : ((mat == 1) ? Wk : Wv);
    g_W16[idx] = pack_h2(W[(2 * k2) * H + n], W[(2 * k2 + 1) * H + n]);
}

// ---------------------------------------------------------------------------
// Kernel 1: fused QKV projection — round-11 version VERBATIM (proven 24us).
// 256 threads = 8 warps as 4(M) x 2(N); warp tile 32 rows x 32 cols x 3 mats
// (A frags reused 3x). x read once chip-wide; x/W double-buffered.
// ---------------------------------------------------------------------------
#define AS2_STR 20
#define WT_STR 68

__global__ __launch_bounds__(256) void qkv_proj_kernel(const float* __restrict__ x)
{
    __shared__ uint32_t As2[2][128][AS2_STR];
    __shared__ uint32_t Wt[2][3][16][WT_STR];

    const int tid  = threadIdx.x;
    const int lane = tid & 31;
    const int wid  = tid >> 5;
    const int warpM = wid & 3;
    const int warpN = wid >> 2;
    const int g  = lane >> 2;
    const int tg = lane & 3;
    const int row0 = blockIdx.x * 128;

    float c[3][2][4][4];
    #pragma unroll
    for (int mat = 0; mat < 3; ++mat)
        #pragma unroll
        for (int mf = 0; mf < 2; ++mf)
            #pragma unroll
            for (int nf = 0; nf < 4; ++nf)
                #pragma unroll
                for (int j = 0; j < 4; ++j) c[mat][mf][nf][j] = 0.0f;

    #pragma unroll
    for (int i = 0; i < 4; ++i) {
        int s = tid + i * 256;
        int r = s >> 3;
        int c4 = (s & 7) * 4;
        float4 v = *(const float4*)&x[(row0 + r) * C + c4];
        *(uint2*)&As2[0][r][c4 >> 1] = make_uint2(pack_h2(v.x, v.y), pack_h2(v.z, v.w));
    }
    #pragma unroll
    for (int i = 0; i < 3; ++i) {
        int s = tid + i * 256;
        int mat = s >> 8, k2 = (s >> 4) & 15, n4 = (s & 15) * 4;
        *(uint4*)&Wt[0][mat][k2][n4] =
            *(const uint4*)&g_W16[mat * (192 * 64) + k2 * 64 + n4];
    }

    for (int kt = 0; kt < 12; ++kt) {
        const int buf = kt & 1;
        __syncthreads();

        float4 xv[4];
        uint4 wv[3];
        const bool pf = (kt < 11);
        if (pf) {
            #pragma unroll
            for (int i = 0; i < 4; ++i) {
                int s = tid + i * 256;
                int r = s >> 3;
                int c4 = (s & 7) * 4;
                xv[i] = *(const float4*)&x[(row0 + r) * C + (kt + 1) * 32 + c4];
            }
            #pragma unroll
            for (int i = 0; i < 3; ++i) {
                int s = tid + i * 256;
                int mat = s >> 8, k2 = (s >> 4) & 15, n4 = (s & 15) * 4;
                wv[i] = *(const uint4*)&g_W16[mat * (192 * 64) + ((kt + 1) * 16 + k2) * 64 + n4];
            }
        }

        #pragma unroll
        for (int ks = 0; ks < 2; ++ks) {
            const int p = ks * 8 + tg;
            uint32_t a[2][4];
            #pragma unroll
            for (int mf = 0; mf < 2; ++mf) {
                int r = warpM * 32 + mf * 16 + g;
                a[mf][0] = As2[buf][r][p];
                a[mf][1] = As2[buf][r + 8][p];
                a[mf][2] = As2[buf][r][p + 4];
                a[mf][3] = As2[buf][r + 8][p + 4];
            }
            #pragma unroll
            for (int mat = 0; mat < 3; ++mat) {
                #pragma unroll
                for (int nf = 0; nf < 4; ++nf) {
                    int n = warpN * 32 + nf * 8 + g;
                    uint32_t b0 = Wt[buf][mat][p][n];
                    uint32_t b1 = Wt[buf][mat][p + 4][n];
                    #pragma unroll
                    for (int mf = 0; mf < 2; ++mf)
                        mma_f16(c[mat][mf][nf], a[mf], b0, b1);
                }
            }
        }

        if (pf) {
            #pragma unroll
            for (int i = 0; i < 4; ++i) {
                int s = tid + i * 256;
                int r = s >> 3;
                int c4 = (s & 7) * 4;
                *(uint2*)&As2[buf ^ 1][r][c4 >> 1] =
                    make_uint2(pack_h2(xv[i].x, xv[i].y), pack_h2(xv[i].z, xv[i].w));
            }
            #pragma unroll
            for (int i = 0; i < 3; ++i) {
                int s = tid + i * 256;
                int mat = s >> 8, k2 = (s >> 4) & 15, n4 = (s & 15) * 4;
                *(uint4*)&Wt[buf ^ 1][mat][k2][n4] = wv[i];
            }
        }
    }

    #pragma unroll
    for (int mat = 0; mat < 3; ++mat) {
        __half* O = (mat == 0) ? g_Q : ((mat == 1) ? g_K : g_V);
        #pragma unroll
        for (int mf = 0; mf < 2; ++mf) {
            int r = row0 + warpM * 32 + mf * 16 + g;
            #pragma unroll
            for (int nf = 0; nf < 4; ++nf) {
                int col = warpN * 32 + nf * 8 + 2 * tg;
                *(uint32_t*)&O[r * H + col] =
                    pack_h2(c[mat][mf][nf][0], c[mat][mf][nf][1]);
                *(uint32_t*)&O[(r + 8) * H + col] =
                    pack_h2(c[mat][mf][nf][2], c[mat][mf][nf][3]);
            }
        }
    }
}

// ---------------------------------------------------------------------------
// Kernel 2: causal flash attention — round-11 base, K prefetch via cp.async
// (V keeps register staging for the byte_perm pairing transform).
// 128 q-rows per block (8 warps, 256 thr), double-buffered K/V, P in regs,
// one barrier per tile. 256 blocks, balanced co-residency.
// ---------------------------------------------------------------------------
#define Q2_STR 36
#define K2_STR 36
#define V2_STR 72
#define ATTN_SMEM_U32 (128 * Q2_STR + 2 * 64 * K2_STR + 2 * 32 * V2_STR)
#define ATTN_SMEM_BYTES (ATTN_SMEM_U32 * 4)

__global__ __launch_bounds__(256) void attn_kernel(float* __restrict__ out)
{
    extern __shared__ uint32_t sm_at[];
    uint32_t* Qs2 = sm_at;                               // [128][36]
    uint32_t (*K2)[64 * K2_STR] =
        (uint32_t (*)[64 * K2_STR])(sm_at + 128 * Q2_STR);
    uint32_t (*V2)[32 * V2_STR] =
        (uint32_t (*)[32 * V2_STR])(sm_at + 128 * Q2_STR + 2 * 64 * K2_STR);

    const int tid  = threadIdx.x;
    const int lane = tid & 31;
    const int wid  = tid >> 5;
    const int g    = lane >> 2;
    const int tg   = lane & 3;

    int bid = blockIdx.x;
    int b, qb;
    if (bid < 148) { qb = bid & 3; b = bid >> 2; }
    else { int s = bid - 148; qb = 3 - (s & 3); b = 37 + (s >> 2); }

    const int tmax = 2 * qb + 1;
    const float scale = 0.125f;

    // per-thread K cp.async coords (2 x 16B per thread per tile)
    const int kr0 = tid >> 3;              // rows 0..31  (s = tid)
    const int kc0 = (tid & 7) * 4;
    const int kr1 = (tid + 256) >> 3;      // rows 32..63
    const int kc1 = kc0;
    uint32_t kdst0[2], kdst1[2];
    #pragma unroll
    for (int bb = 0; bb < 2; ++bb) {
        kdst0[bb] = smem_addr_u32(&K2[bb][kr0 * K2_STR + kc0]);
        kdst1[bb] = smem_addr_u32(&K2[bb][kr1 * K2_STR + kc1]);
    }

    // ---- Q tile ----
    {
        const uint4* qsrc = (const uint4*)(g_Q + (b * T + qb * 128) * H);
        #pragma unroll
        for (int i = 0; i < 4; ++i) {
            int s = tid + i * 256;
            int r = s >> 3;
            int c4 = (s & 7) * 4;
            *(uint4*)&Qs2[r * Q2_STR + c4] = qsrc[s];
        }
    }
    // ---- K/V tile 0 into buf 0 ----
    {
        const __half* kbase = g_K + (b * T) * H;
        cp_async16(kdst0[0], kbase + kr0 * H + kc0 * 2);
        cp_async16(kdst1[0], kbase + kr1 * H + kc1 * 2);
        cp_async_commit();
        {
            int k2 = tid >> 3;
            int h0 = (tid & 7) * 8;
            const __half* vb = g_V + (b * T + 2 * k2) * H + h0;
            uint4 ea = *(const uint4*)vb;
            uint4 eb = *(const uint4*)(vb + H);
            uint32_t* dst = &V2[0][k2 * V2_STR + h0];
            *(uint4*)&dst[0] = make_uint4(
                __byte_perm(ea.x, eb.x, 0x5410), __byte_perm(ea.x, eb.x, 0x7632),
                __byte_perm(ea.y, eb.y, 0x5410), __byte_perm(ea.y, eb.y, 0x7632));
            *(uint4*)&dst[4] = make_uint4(
                __byte_perm(ea.z, eb.z, 0x5410), __byte_perm(ea.z, eb.z, 0x7632),
                __byte_perm(ea.w, eb.w, 0x5410), __byte_perm(ea.w, eb.w, 0x7632));
        }
        cp_async_wait0();
    }
    __syncthreads();

    // ---- Q fragments (register resident) ----
    uint32_t qa[4][4];
    const int qrow = wid * 16 + g;
    #pragma unroll
    for (int ks = 0; ks < 4; ++ks) {
        int p = ks * 8 + tg;
        qa[ks][0] = Qs2[qrow * Q2_STR + p];
        qa[ks][1] = Qs2[(qrow + 8) * Q2_STR + p];
        qa[ks][2] = Qs2[qrow * Q2_STR + p + 4];
        qa[ks][3] = Qs2[(qrow + 8) * Q2_STR + p + 4];
    }

    float m[2] = {-1e30f, -1e30f};
    float l[2] = {0.0f, 0.0f};
    float o[8][4];
    #pragma unroll
    for (int nf = 0; nf < 8; ++nf)
        #pragma unroll
        for (int j = 0; j < 4; ++j) o[nf][j] = 0.0f;

    const int rowg0 = qb * 128 + wid * 16 + g;

    for (int t = 0; t <= tmax; ++t) {
        const int buf = t & 1;
        const bool pf = (t < tmax);

        uint4 ve, vo;
        if (pf) {
            // K prefetch straight to smem (no register staging)
            const __half* kbase = g_K + (b * T + (t + 1) * 64) * H;
            cp_async16(kdst0[buf ^ 1], kbase + kr0 * H + kc0 * 2);
            cp_async16(kdst1[buf ^ 1], kbase + kr1 * H + kc1 * 2);
            cp_async_commit();
            // V prefetch (register staged for pairing transform)
            int k2 = tid >> 3;
            int h0 = (tid & 7) * 8;
            const __half* vb = g_V + (b * T + (t + 1) * 64 + 2 * k2) * H + h0;
            ve = *(const uint4*)vb;
            vo = *(const uint4*)(vb + H);
        }

        // --- S = Q K^T ---
        float sf[8][4];
        #pragma unroll
        for (int nf = 0; nf < 8; ++nf)
            #pragma unroll
            for (int j = 0; j < 4; ++j) sf[nf][j] = 0.0f;

        #pragma unroll
        for (int ks = 0; ks < 4; ++ks) {
            const int p = ks * 8 + tg;
            #pragma unroll
            for (int nf = 0; nf < 8; ++nf) {
                int key = nf * 8 + g;
                mma_f16(sf[nf], qa[ks],
                        K2[buf][key * K2_STR + p], K2[buf][key * K2_STR + p + 4]);
            }
        }

        if (pf) {
            int k2 = tid >> 3;
            int h0 = (tid & 7) * 8;
            uint32_t* dst = &V2[buf ^ 1][k2 * V2_STR + h0];
            *(uint4*)&dst[0] = make_uint4(
                __byte_perm(ve.x, vo.x, 0x5410), __byte_perm(ve.x, vo.x, 0x7632),
                __byte_perm(ve.y, vo.y, 0x5410), __byte_perm(ve.y, vo.y, 0x7632));
            *(uint4*)&dst[4] = make_uint4(
                __byte_perm(ve.z, vo.z, 0x5410), __byte_perm(ve.z, vo.z, 0x7632),
                __byte_perm(ve.w, vo.w, 0x5410), __byte_perm(ve.w, vo.w, 0x7632));
        }

        // --- online softmax ---
        const bool maskit = (t >= 2 * qb);
        float mnew[2] = {m[0], m[1]};
        #pragma unroll
        for (int nf = 0; nf < 8; ++nf)
            #pragma unroll
            for (int j = 0; j < 4; ++j) {
                int rr = j >> 1;
                float v = sf[nf][j] * scale;
                if (maskit) {
                    int col = t * 64 + nf * 8 + 2 * tg + (j & 1);
                    int row = rowg0 + rr * 8;
                    if (col > row) v = -1e30f;
                }
                sf[nf][j] = v;
                mnew[rr] = fmaxf(mnew[rr], v);
            }
        #pragma unroll
        for (int rr = 0; rr < 2; ++rr) {
            mnew[rr] = fmaxf(mnew[rr], __shfl_xor_sync(0xffffffffu, mnew[rr], 1));
            mnew[rr] = fmaxf(mnew[rr], __shfl_xor_sync(0xffffffffu, mnew[rr], 2));
        }
        float alpha[2];
        #pragma unroll
        for (int rr = 0; rr < 2; ++rr) {
            alpha[rr] = __expf(m[rr] - mnew[rr]);
            m[rr] = mnew[rr];
        }
        float ls[2] = {0.0f, 0.0f};
        #pragma unroll
        for (int nf = 0; nf < 8; ++nf)
            #pragma unroll
            for (int j = 0; j < 4; ++j) {
                int rr = j >> 1;
                float pexp = __expf(sf[nf][j] - m[rr]);
                sf[nf][j] = pexp;
                ls[rr] += pexp;
            }
        #pragma unroll
        for (int rr = 0; rr < 2; ++rr) {
            ls[rr] += __shfl_xor_sync(0xffffffffu, ls[rr], 1);
            ls[rr] += __shfl_xor_sync(0xffffffffu, ls[rr], 2);
            l[rr] = l[rr] * alpha[rr] + ls[rr];
        }
        #pragma unroll
        for (int nf = 0; nf < 8; ++nf) {
            o[nf][0] *= alpha[0];
            o[nf][1] *= alpha[0];
            o[nf][2] *= alpha[1];
            o[nf][3] *= alpha[1];
        }

        // --- O += P V ---
        #pragma unroll
        for (int ks = 0; ks < 4; ++ks) {
            uint32_t pa[4];
            pa[0] = pack_h2(sf[2 * ks][0],     sf[2 * ks][1]);
            pa[1] = pack_h2(sf[2 * ks][2],     sf[2 * ks][3]);
            pa[2] = pack_h2(sf[2 * ks + 1][0], sf[2 * ks + 1][1]);
            pa[3] = pack_h2(sf[2 * ks + 1][2], sf[2 * ks + 1][3]);
            #pragma unroll
            for (int nf = 0; nf < 8; ++nf) {
                int hh = nf * 8 + g;
                mma_f16(o[nf], pa,
                        V2[buf][(ks * 8 + tg) * V2_STR + hh],
                        V2[buf][(ks * 8 + tg + 4) * V2_STR + hh]);
            }
        }

        if (pf) cp_async_wait0();
        __syncthreads();
    }

    const float inv0 = 1.0f / l[0];
    const float inv1 = 1.0f / l[1];
    const int grow = b * T + qb * 128 + wid * 16 + g;
    #pragma unroll
    for (int nf = 0; nf < 8; ++nf) {
        int col = nf * 8 + 2 * tg;
        *(float2*)&out[grow * H + col] =
            make_float2(o[nf][0] * inv0, o[nf][1] * inv0);
        *(float2*)&out[(grow + 8) * H + col] =
            make_float2(o[nf][2] * inv1, o[nf][3] * inv1);
    }
}

// ---------------------------------------------------------------------------
extern "C" void kernel_launch(void* const* d_in, const int* in_sizes, int n_in,
                              void* d_out, int out_size)
{
    const float* x  = (const float*)d_in[0];
    const float* Wq = (const float*)d_in[1];
    const float* Wk = (const float*)d_in[2];
    const float* Wv = (const float*)d_in[3];
    float* out = (float*)d_out;

    pack_w_kernel<<<144, 256>>>(Wq, Wk, Wv);

    qkv_proj_kernel<<<BT / 128, 256>>>(x);

    cudaFuncSetAttribute(attn_kernel,
                         cudaFuncAttributeMaxDynamicSharedMemorySize,
                         ATTN_SMEM_BYTES);
    attn_kernel<<<256, 256, ATTN_SMEM_BYTES>>>(out);
}

// round 15
// speedup vs baseline: 1.2436x; 1.1245x over previous
#include <cuda_runtime.h>
#include <cuda_fp16.h>
#include <cstdint>

#define BATCH 64
#define T 512
#define C 384
#define H 64
#define BT (BATCH*T)

// Q (pre-scaled by 0.125*log2e), K, V projected fp16 row-major [row*H+col].
__device__ __half g_Q[BT * H];
__device__ __half g_K[BT * H];
__device__ __half g_V[BT * H];
__device__ uint32_t g_W16[3 * 192 * 64];

#define QSCALE 0.180336879f   // 0.125 * log2(e)

__device__ __forceinline__ uint32_t pack_h2(float a, float b) {
    __half2 h = __floats2half2_rn(a, b);
    return *(uint32_t*)&h;
}

__device__ __forceinline__ void mma_f16(float c[4], const uint32_t a[4],
                                        uint32_t b0, uint32_t b1) {
    asm volatile(
        "mma.sync.aligned.m16n8k16.row.col.f32.f16.f16.f32 "
        "{%0,%1,%2,%3}, {%4,%5,%6,%7}, {%8,%9}, {%0,%1,%2,%3};\n"
        : "+f"(c[0]), "+f"(c[1]), "+f"(c[2]), "+f"(c[3])
        : "r"(a[0]), "r"(a[1]), "r"(a[2]), "r"(a[3]), "r"(b0), "r"(b1));
}

// ---------------------------------------------------------------------------
// Kernel 0: pack W fp32 -> fp16 half2 pairs along k.
// ---------------------------------------------------------------------------
__global__ __launch_bounds__(256) void pack_w_kernel(
    const float* __restrict__ Wq,
    const float* __restrict__ Wk,
    const float* __restrict__ Wv)
{
    int idx = blockIdx.x * 256 + threadIdx.x;
    int mat = idx / (192 * 64);
    int rem = idx - mat * (192 * 64);
    int k2 = rem >> 6;
    int n  = rem & 63;
    const float* W = (mat == 0) ? Wq : ((mat == 1) ? Wk : Wv);
    g_W16[idx] = pack_h2(W[(2 * k2) * H + n], W[(2 * k2 + 1) * H + n]);
}

// ---------------------------------------------------------------------------
// Kernel 1: fused QKV projection (round-11 structure). Q scaled by QSCALE.
// ---------------------------------------------------------------------------
#define AS2_STR 20
#define WT_STR 68

__global__ __launch_bounds__(256) void qkv_proj_kernel(const float* __restrict__ x)
{
    __shared__ uint32_t As2[2][128][AS2_STR];
    __shared__ uint32_t Wt[2][3][16][WT_STR];

    const int tid  = threadIdx.x;
    const int lane = tid & 31;
    const int wid  = tid >> 5;
    const int warpM = wid & 3;
    const int warpN = wid >> 2;
    const int g  = lane >> 2;
    const int tg = lane & 3;
    const int row0 = blockIdx.x * 128;

    float c[3][2][4][4];
    #pragma unroll
    for (int mat = 0; mat < 3; ++mat)
        #pragma unroll
        for (int mf = 0; mf < 2; ++mf)
            #pragma unroll
            for (int nf = 0; nf < 4; ++nf)
                #pragma unroll
                for (int j = 0; j < 4; ++j) c[mat][mf][nf][j] = 0.0f;

    #pragma unroll
    for (int i = 0; i < 4; ++i) {
        int s = tid + i * 256;
        int r = s >> 3;
        int c4 = (s & 7) * 4;
        float4 v = *(const float4*)&x[(row0 + r) * C + c4];
        *(uint2*)&As2[0][r][c4 >> 1] = make_uint2(pack_h2(v.x, v.y), pack_h2(v.z, v.w));
    }
    #pragma unroll
    for (int i = 0; i < 3; ++i) {
        int s = tid + i * 256;
        int mat = s >> 8, k2 = (s >> 4) & 15, n4 = (s & 15) * 4;
        *(uint4*)&Wt[0][mat][k2][n4] =
            *(const uint4*)&g_W16[mat * (192 * 64) + k2 * 64 + n4];
    }

    for (int kt = 0; kt < 12; ++kt) {
        const int buf = kt & 1;
        __syncthreads();

        float4 xv[4];
        uint4 wv[3];
        const bool pf = (kt < 11);
        if (pf) {
            #pragma unroll
            for (int i = 0; i < 4; ++i) {
                int s = tid + i * 256;
                int r = s >> 3;
                int c4 = (s & 7) * 4;
                xv[i] = *(const float4*)&x[(row0 + r) * C + (kt + 1) * 32 + c4];
            }
            #pragma unroll
            for (int i = 0; i < 3; ++i) {
                int s = tid + i * 256;
                int mat = s >> 8, k2 = (s >> 4) & 15, n4 = (s & 15) * 4;
                wv[i] = *(const uint4*)&g_W16[mat * (192 * 64) + ((kt + 1) * 16 + k2) * 64 + n4];
            }
        }

        #pragma unroll
        for (int ks = 0; ks < 2; ++ks) {
            const int p = ks * 8 + tg;
            uint32_t a[2][4];
            #pragma unroll
            for (int mf = 0; mf < 2; ++mf) {
                int r = warpM * 32 + mf * 16 + g;
                a[mf][0] = As2[buf][r][p];
                a[mf][1] = As2[buf][r + 8][p];
                a[mf][2] = As2[buf][r][p + 4];
                a[mf][3] = As2[buf][r + 8][p + 4];
            }
            #pragma unroll
            for (int mat = 0; mat < 3; ++mat) {
                #pragma unroll
                for (int nf = 0; nf < 4; ++nf) {
                    int n = warpN * 32 + nf * 8 + g;
                    uint32_t b0 = Wt[buf][mat][p][n];
                    uint32_t b1 = Wt[buf][mat][p + 4][n];
                    #pragma unroll
                    for (int mf = 0; mf < 2; ++mf)
                        mma_f16(c[mat][mf][nf], a[mf], b0, b1);
                }
            }
        }

        if (pf) {
            #pragma unroll
            for (int i = 0; i < 4; ++i) {
                int s = tid + i * 256;
                int r = s >> 3;
                int c4 = (s & 7) * 4;
                *(uint2*)&As2[buf ^ 1][r][c4 >> 1] =
                    make_uint2(pack_h2(xv[i].x, xv[i].y), pack_h2(xv[i].z, xv[i].w));
            }
            #pragma unroll
            for (int i = 0; i < 3; ++i) {
                int s = tid + i * 256;
                int mat = s >> 8, k2 = (s >> 4) & 15, n4 = (s & 15) * 4;
                *(uint4*)&Wt[buf ^ 1][mat][k2][n4] = wv[i];
            }
        }
    }

    #pragma unroll
    for (int mat = 0; mat < 3; ++mat) {
        __half* O = (mat == 0) ? g_Q : ((mat == 1) ? g_K : g_V);
        const float sc = (mat == 0) ? QSCALE : 1.0f;
        #pragma unroll
        for (int mf = 0; mf < 2; ++mf) {
            int r = row0 + warpM * 32 + mf * 16 + g;
            #pragma unroll
            for (int nf = 0; nf < 4; ++nf) {
                int col = warpN * 32 + nf * 8 + 2 * tg;
                *(uint32_t*)&O[r * H + col] =
                    pack_h2(c[mat][mf][nf][0] * sc, c[mat][mf][nf][1] * sc);
                *(uint32_t*)&O[(r + 8) * H + col] =
                    pack_h2(c[mat][mf][nf][2] * sc, c[mat][mf][nf][3] * sc);
            }
        }
    }
}

// ---------------------------------------------------------------------------
// Kernel 2: causal flash attention — round-11 base + log2-domain softmax
// (scores arrive pre-scaled; bare exp2f), per-lane mask predicate, and
// fully-masked last-tile skip for warps 0-3.
// ---------------------------------------------------------------------------
#define Q2_STR 36
#define K2_STR 36
#define V2_STR 72
#define ATTN_SMEM_U32 (128 * Q2_STR + 2 * 64 * K2_STR + 2 * 32 * V2_STR)
#define ATTN_SMEM_BYTES (ATTN_SMEM_U32 * 4)

__global__ __launch_bounds__(256) void attn_kernel(float* __restrict__ out)
{
    extern __shared__ uint32_t sm_at[];
    uint32_t* Qs2 = sm_at;                               // [128][36]
    uint32_t (*K2)[64 * K2_STR] =
        (uint32_t (*)[64 * K2_STR])(sm_at + 128 * Q2_STR);
    uint32_t (*V2)[32 * V2_STR] =
        (uint32_t (*)[32 * V2_STR])(sm_at + 128 * Q2_STR + 2 * 64 * K2_STR);

    const int tid  = threadIdx.x;
    const int lane = tid & 31;
    const int wid  = tid >> 5;
    const int g    = lane >> 2;
    const int tg   = lane & 3;

    int bid = blockIdx.x;
    int b, qb;
    if (bid < 148) { qb = bid & 3; b = bid >> 2; }
    else { int s = bid - 148; qb = 3 - (s & 3); b = 37 + (s >> 2); }

    const int tmax = 2 * qb + 1;

    // ---- Q tile ----
    {
        const uint4* qsrc = (const uint4*)(g_Q + (b * T + qb * 128) * H);
        #pragma unroll
        for (int i = 0; i < 4; ++i) {
            int s = tid + i * 256;
            int r = s >> 3;
            int c4 = (s & 7) * 4;
            *(uint4*)&Qs2[r * Q2_STR + c4] = qsrc[s];
        }
    }
    // ---- K/V tile 0 into buf 0 ----
    {
        const uint4* ksrc = (const uint4*)(g_K + (b * T) * H);
        #pragma unroll
        for (int i = 0; i < 2; ++i) {
            int s = tid + i * 256;
            *(uint4*)&K2[0][(s >> 3) * K2_STR + (s & 7) * 4] = ksrc[s];
        }
        {
            int k2 = tid >> 3;
            int h0 = (tid & 7) * 8;
            const __half* vb = g_V + (b * T + 2 * k2) * H + h0;
            uint4 ea = *(const uint4*)vb;
            uint4 eb = *(const uint4*)(vb + H);
            uint32_t* dst = &V2[0][k2 * V2_STR + h0];
            *(uint4*)&dst[0] = make_uint4(
                __byte_perm(ea.x, eb.x, 0x5410), __byte_perm(ea.x, eb.x, 0x7632),
                __byte_perm(ea.y, eb.y, 0x5410), __byte_perm(ea.y, eb.y, 0x7632));
            *(uint4*)&dst[4] = make_uint4(
                __byte_perm(ea.z, eb.z, 0x5410), __byte_perm(ea.z, eb.z, 0x7632),
                __byte_perm(ea.w, eb.w, 0x5410), __byte_perm(ea.w, eb.w, 0x7632));
        }
    }
    __syncthreads();

    // ---- Q fragments ----
    uint32_t qa[4][4];
    const int qrow = wid * 16 + g;
    #pragma unroll
    for (int ks = 0; ks < 4; ++ks) {
        int p = ks * 8 + tg;
        qa[ks][0] = Qs2[qrow * Q2_STR + p];
        qa[ks][1] = Qs2[(qrow + 8) * Q2_STR + p];
        qa[ks][2] = Qs2[qrow * Q2_STR + p + 4];
        qa[ks][3] = Qs2[(qrow + 8) * Q2_STR + p + 4];
    }

    float m[2] = {-1e30f, -1e30f};
    float l[2] = {0.0f, 0.0f};
    float o[8][4];
    #pragma unroll
    for (int nf = 0; nf < 8; ++nf)
        #pragma unroll
        for (int j = 0; j < 4; ++j) o[nf][j] = 0.0f;

    const int rowg0 = qb * 128 + wid * 16 + g;

    for (int t = 0; t <= tmax; ++t) {
        const int buf = t & 1;
        const bool pf = (t < tmax);

        uint4 kp[2], ve, vo;
        if (pf) {
            const uint4* ksrc = (const uint4*)(g_K + (b * T + (t + 1) * 64) * H);
            #pragma unroll
            for (int i = 0; i < 2; ++i) kp[i] = ksrc[tid + i * 256];
            {
                int k2 = tid >> 3;
                int h0 = (tid & 7) * 8;
                const __half* vb = g_V + (b * T + (t + 1) * 64 + 2 * k2) * H + h0;
                ve = *(const uint4*)vb;
                vo = *(const uint4*)(vb + H);
            }
        }

        // warps 0-3 at t == tmax: tile is entirely above the diagonal -> skip
        const bool active = (t != tmax) || (wid >= 4);

        if (active) {
            // --- S = Q K^T (scores already scaled * log2e) ---
            float sf[8][4];
            #pragma unroll
            for (int nf = 0; nf < 8; ++nf)
                #pragma unroll
                for (int j = 0; j < 4; ++j) sf[nf][j] = 0.0f;

            #pragma unroll
            for (int ks = 0; ks < 4; ++ks) {
                const int p = ks * 8 + tg;
                #pragma unroll
                for (int nf = 0; nf < 8; ++nf) {
                    int key = nf * 8 + g;
                    mma_f16(sf[nf], qa[ks],
                            K2[buf][key * K2_STR + p], K2[buf][key * K2_STR + p + 4]);
                }
            }

            if (pf) {
                #pragma unroll
                for (int i = 0; i < 2; ++i) {
                    int s = tid + i * 256;
                    *(uint4*)&K2[buf ^ 1][(s >> 3) * K2_STR + (s & 7) * 4] = kp[i];
                }
                {
                    int k2 = tid >> 3;
                    int h0 = (tid & 7) * 8;
                    uint32_t* dst = &V2[buf ^ 1][k2 * V2_STR + h0];
                    *(uint4*)&dst[0] = make_uint4(
                        __byte_perm(ve.x, vo.x, 0x5410), __byte_perm(ve.x, vo.x, 0x7632),
                        __byte_perm(ve.y, vo.y, 0x5410), __byte_perm(ve.y, vo.y, 0x7632));
                    *(uint4*)&dst[4] = make_uint4(
                        __byte_perm(ve.z, vo.z, 0x5410), __byte_perm(ve.z, vo.z, 0x7632),
                        __byte_perm(ve.w, vo.w, 0x5410), __byte_perm(ve.w, vo.w, 0x7632));
                }
            }

            // --- online softmax (log2 domain) ---
            const bool maskit = (t * 64 + 63 > rowg0);
            float mnew[2] = {m[0], m[1]};
            #pragma unroll
            for (int nf = 0; nf < 8; ++nf)
                #pragma unroll
                for (int j = 0; j < 4; ++j) {
                    int rr = j >> 1;
                    float v = sf[nf][j];
                    if (maskit) {
                        int col = t * 64 + nf * 8 + 2 * tg + (j & 1);
                        int row = rowg0 + rr * 8;
                        if (col > row) v = -1e30f;
                    }
                    sf[nf][j] = v;
                    mnew[rr] = fmaxf(mnew[rr], v);
                }
            #pragma unroll
            for (int rr = 0; rr < 2; ++rr) {
                mnew[rr] = fmaxf(mnew[rr], __shfl_xor_sync(0xffffffffu, mnew[rr], 1));
                mnew[rr] = fmaxf(mnew[rr], __shfl_xor_sync(0xffffffffu, mnew[rr], 2));
            }
            float alpha[2];
            #pragma unroll
            for (int rr = 0; rr < 2; ++rr) {
                alpha[rr] = exp2f(m[rr] - mnew[rr]);
                m[rr] = mnew[rr];
            }
            float ls[2] = {0.0f, 0.0f};
            #pragma unroll
            for (int nf = 0; nf < 8; ++nf)
                #pragma unroll
                for (int j = 0; j < 4; ++j) {
                    int rr = j >> 1;
                    float pexp = exp2f(sf[nf][j] - m[rr]);
                    sf[nf][j] = pexp;
                    ls[rr] += pexp;
                }
            #pragma unroll
            for (int rr = 0; rr < 2; ++rr) {
                ls[rr] += __shfl_xor_sync(0xffffffffu, ls[rr], 1);
                ls[rr] += __shfl_xor_sync(0xffffffffu, ls[rr], 2);
                l[rr] = l[rr] * alpha[rr] + ls[rr];
            }
            #pragma unroll
            for (int nf = 0; nf < 8; ++nf) {
                o[nf][0] *= alpha[0];
                o[nf][1] *= alpha[0];
                o[nf][2] *= alpha[1];
                o[nf][3] *= alpha[1];
            }

            // --- O += P V ---
            #pragma unroll
            for (int ks = 0; ks < 4; ++ks) {
                uint32_t pa[4];
                pa[0] = pack_h2(sf[2 * ks][0],     sf[2 * ks][1]);
                pa[1] = pack_h2(sf[2 * ks][2],     sf[2 * ks][3]);
                pa[2] = pack_h2(sf[2 * ks + 1][0], sf[2 * ks + 1][1]);
                pa[3] = pack_h2(sf[2 * ks + 1][2], sf[2 * ks + 1][3]);
                #pragma unroll
                for (int nf = 0; nf < 8; ++nf) {
                    int hh = nf * 8 + g;
                    mma_f16(o[nf], pa,
                            V2[buf][(ks * 8 + tg) * V2_STR + hh],
                            V2[buf][(ks * 8 + tg + 4) * V2_STR + hh]);
                }
            }
        }

        __syncthreads();
    }

    const float inv0 = 1.0f / l[0];
    const float inv1 = 1.0f / l[1];
    const int grow = b * T + qb * 128 + wid * 16 + g;
    #pragma unroll
    for (int nf = 0; nf < 8; ++nf) {
        int col = nf * 8 + 2 * tg;
        *(float2*)&out[grow * H + col] =
            make_float2(o[nf][0] * inv0, o[nf][1] * inv0);
        *(float2*)&out[(grow + 8) * H + col] =
            make_float2(o[nf][2] * inv1, o[nf][3] * inv1);
    }
}

// ---------------------------------------------------------------------------
extern "C" void kernel_launch(void* const* d_in, const int* in_sizes, int n_in,
                              void* d_out, int out_size)
{
    const float* x  = (const float*)d_in[0];
    const float* Wq = (const float*)d_in[1];
    const float* Wk = (const float*)d_in[2];
    const float* Wv = (const float*)d_in[3];
    float* out = (float*)d_out;

    pack_w_kernel<<<144, 256>>>(Wq, Wk, Wv);

    qkv_proj_kernel<<<BT / 128, 256>>>(x);

    cudaFuncSetAttribute(attn_kernel,
                         cudaFuncAttributeMaxDynamicSharedMemorySize,
                         ATTN_SMEM_BYTES);
    attn_kernel<<<256, 256, ATTN_SMEM_BYTES>>>(out);
}